// round 1
// baseline (speedup 1.0000x reference)
#include <cuda_runtime.h>
#include <math.h>

#define BATCH  8
#define SEQ    577
#define DIM    768
#define HEADS  12
#define HDIM   64
#define MLPD   3072
#define DEPTH  8
#define NPATCH 576
#define PDIM   768
#define IMGH   384
#define PSZ    16
#define HP     24

// ---------------- scratch (device globals; allocation is banned) ------------
__device__ float g_X  [BATCH * SEQ * DIM];        // residual stream
__device__ float g_Y  [BATCH * SEQ * DIM];        // LN output / patch-embed tmp
__device__ float g_QKV[BATCH * SEQ * 3 * DIM];    // fused qkv
__device__ float g_S  [BATCH * HEADS * SEQ * SEQ];// attention scores
__device__ float g_O  [BATCH * SEQ * DIM];        // attn output (pre-proj)
__device__ float g_H  [BATCH * SEQ * MLPD];       // mlp hidden
__device__ float g_P  [BATCH * NPATCH * PDIM];    // patchified image

// ---------------- generic batched tiled SGEMM -------------------------------
// C[z] = op( A[z] @ B[z] (+ bias) ), fuse: 0=none, 1=gelu(exact), 2=residual add
#define BM 64
#define BN 64
#define BK 16

__global__ void __launch_bounds__(256)
gemm_kernel(const float* __restrict__ A, int lda, long long sAb, long long sAh,
            const float* __restrict__ Bm, int ldb, long long sBb, long long sBh, int transB,
            const float* __restrict__ bias,
            float* __restrict__ C, int ldc, long long sCb, long long sCh,
            int M, int N, int K, int fuse)
{
    int z  = blockIdx.z;
    int zb = z / HEADS, zh = z % HEADS;
    A  += zb * sAb + zh * sAh;
    Bm += zb * sBb + zh * sBh;
    C  += zb * sCb + zh * sCh;

    __shared__ float As[BK][BM];
    __shared__ float Bs[BK][BN + 4];

    int r0 = blockIdx.y * BM;
    int c0 = blockIdx.x * BN;
    int tid = threadIdx.x;
    int ty = tid >> 4, tx = tid & 15;

    float acc[4][4] = {};

    for (int k0 = 0; k0 < K; k0 += BK) {
        // load A tile (BM x BK)
        #pragma unroll
        for (int it = 0; it < 4; it++) {
            int idx = tid + it * 256;
            int r = idx >> 4, kk = idx & 15;
            float v = 0.f;
            if (r0 + r < M && k0 + kk < K)
                v = A[(long long)(r0 + r) * lda + (k0 + kk)];
            As[kk][r] = v;
        }
        // load B tile (BK x BN)
        if (!transB) {
            #pragma unroll
            for (int it = 0; it < 4; it++) {
                int idx = tid + it * 256;
                int kk = idx >> 6, c = idx & 63;
                float v = 0.f;
                if (k0 + kk < K && c0 + c < N)
                    v = Bm[(long long)(k0 + kk) * ldb + (c0 + c)];
                Bs[kk][c] = v;
            }
        } else {
            #pragma unroll
            for (int it = 0; it < 4; it++) {
                int idx = tid + it * 256;
                int c = idx >> 4, kk = idx & 15;
                float v = 0.f;
                if (k0 + kk < K && c0 + c < N)
                    v = Bm[(long long)(c0 + c) * ldb + (k0 + kk)];
                Bs[kk][c] = v;
            }
        }
        __syncthreads();

        #pragma unroll
        for (int kk = 0; kk < BK; kk++) {
            float a[4], b[4];
            #pragma unroll
            for (int i = 0; i < 4; i++) a[i] = As[kk][ty * 4 + i];
            #pragma unroll
            for (int j = 0; j < 4; j++) b[j] = Bs[kk][tx * 4 + j];
            #pragma unroll
            for (int i = 0; i < 4; i++)
                #pragma unroll
                for (int j = 0; j < 4; j++)
                    acc[i][j] += a[i] * b[j];
        }
        __syncthreads();
    }

    #pragma unroll
    for (int i = 0; i < 4; i++) {
        int r = r0 + ty * 4 + i;
        if (r >= M) continue;
        #pragma unroll
        for (int j = 0; j < 4; j++) {
            int c = c0 + tx * 4 + j;
            if (c >= N) continue;
            float v = acc[i][j];
            if (bias) v += bias[c];
            if (fuse == 1) v = 0.5f * v * (1.f + erff(v * 0.70710678118654752f));
            long long off = (long long)r * ldc + c;
            if (fuse == 2) v += C[off];
            C[off] = v;
        }
    }
}

// ---------------- reductions -------------------------------------------------
__device__ __forceinline__ float blockReduceSum(float v, volatile float* sh) {
    int lane = threadIdx.x & 31, w = threadIdx.x >> 5;
    #pragma unroll
    for (int o = 16; o; o >>= 1) v += __shfl_down_sync(0xffffffffu, v, o);
    if (lane == 0) sh[w] = v;
    __syncthreads();
    if (threadIdx.x < 32) {
        v = (threadIdx.x < 8) ? sh[threadIdx.x] : 0.f;
        #pragma unroll
        for (int o = 4; o; o >>= 1) v += __shfl_down_sync(0xffffffffu, v, o);
        if (lane == 0) sh[0] = v;
    }
    __syncthreads();
    return sh[0];
}

__device__ __forceinline__ float blockReduceMax(float v, volatile float* sh) {
    int lane = threadIdx.x & 31, w = threadIdx.x >> 5;
    #pragma unroll
    for (int o = 16; o; o >>= 1) v = fmaxf(v, __shfl_down_sync(0xffffffffu, v, o));
    if (lane == 0) sh[w] = v;
    __syncthreads();
    if (threadIdx.x < 32) {
        v = (threadIdx.x < 8) ? sh[threadIdx.x] : -3.0e38f;
        #pragma unroll
        for (int o = 4; o; o >>= 1) v = fmaxf(v, __shfl_down_sync(0xffffffffu, v, o));
        if (lane == 0) sh[0] = v;
    }
    __syncthreads();
    return sh[0];
}

// ---------------- layernorm --------------------------------------------------
__global__ void __launch_bounds__(256)
layernorm_kernel(const float* __restrict__ X, const float* __restrict__ g,
                 const float* __restrict__ b, float* __restrict__ Y)
{
    long long row = blockIdx.x;
    const float* x = X + row * DIM;
    __shared__ float sh0[8], sh1[8];
    float s = 0.f, s2 = 0.f;
    float v0 = x[threadIdx.x], v1 = x[threadIdx.x + 256], v2 = x[threadIdx.x + 512];
    s = v0 + v1 + v2;
    s2 = v0 * v0 + v1 * v1 + v2 * v2;
    float sum  = blockReduceSum(s,  sh0);
    float sum2 = blockReduceSum(s2, sh1);
    float m   = sum * (1.f / DIM);
    float var = sum2 * (1.f / DIM) - m * m;
    float inv = rsqrtf(var + 1e-5f);
    float* y = Y + row * DIM;
    #pragma unroll
    for (int i = 0; i < 3; i++) {
        int c = threadIdx.x + i * 256;
        float xv = (i == 0) ? v0 : (i == 1) ? v1 : v2;
        y[c] = (xv - m) * inv * g[c] + b[c];
    }
}

// ---------------- softmax (in place over last dim SEQ) -----------------------
__global__ void __launch_bounds__(256)
softmax_kernel(float* __restrict__ S)
{
    long long row = blockIdx.x;
    float* p = S + row * SEQ;
    __shared__ float sh[8];
    float mx = -3.0e38f;
    for (int c = threadIdx.x; c < SEQ; c += 256) mx = fmaxf(mx, p[c]);
    mx = blockReduceMax(mx, sh);
    __syncthreads();
    float s = 0.f;
    for (int c = threadIdx.x; c < SEQ; c += 256) {
        float e = __expf(p[c] - mx);
        p[c] = e;
        s += e;
    }
    s = blockReduceSum(s, sh);
    float inv = 1.f / s;
    for (int c = threadIdx.x; c < SEQ; c += 256) p[c] *= inv;
}

// ---------------- patchify: img -> g_P[b*576+patch][ (p1*16+p2)*3 + c ] ------
__global__ void __launch_bounds__(256)
patchify_kernel(const float* __restrict__ img)
{
    int idx = blockIdx.x * 256 + threadIdx.x;
    if (idx >= BATCH * NPATCH * PDIM) return;
    int pd = idx % PDIM;
    int t  = idx / PDIM;
    int patch = t % NPATCH;
    int b     = t / NPATCH;
    int c  = pd % 3;
    int pp = pd / 3;
    int p2 = pp % PSZ, p1 = pp / PSZ;
    int wx = patch % HP, hy = patch / HP;
    g_P[idx] = img[(((long long)b * 3 + c) * IMGH + hy * PSZ + p1) * IMGH + wx * PSZ + p2];
}

// ---------------- assemble: cls + pos add ------------------------------------
__global__ void __launch_bounds__(256)
assemble_kernel(const float* __restrict__ emb, const float* __restrict__ cls,
                const float* __restrict__ pos)
{
    int idx = blockIdx.x * 256 + threadIdx.x;
    if (idx >= BATCH * SEQ * DIM) return;
    int d = idx % DIM;
    int t = idx / DIM;
    int s = t % SEQ;
    int b = t / SEQ;
    float v;
    if (s == 0) v = cls[d] + pos[d];
    else        v = emb[((long long)b * NPATCH + (s - 1)) * DIM + d] + pos[(long long)s * DIM + d];
    g_X[idx] = v;
}

// ---------------- output: drop cls token -------------------------------------
__global__ void __launch_bounds__(256)
output_kernel(float* __restrict__ out)
{
    int idx = blockIdx.x * 256 + threadIdx.x;
    if (idx >= BATCH * NPATCH * DIM) return;
    int d = idx % DIM;
    int t = idx / DIM;
    int s = t % NPATCH;
    int b = t / NPATCH;
    out[idx] = g_X[((long long)b * SEQ + (s + 1)) * DIM + d];
}

// ---------------- host driver ------------------------------------------------
static inline dim3 gemm_grid(int M, int N, int Z) {
    return dim3((N + BN - 1) / BN, (M + BM - 1) / BM, Z);
}

extern "C" void kernel_launch(void* const* d_in, const int* in_sizes, int n_in,
                              void* d_out, int out_size)
{
    const float* img   = (const float*)d_in[0];
    const float* pos   = (const float*)d_in[1];
    const float* cls   = (const float*)d_in[2];
    const float* pw    = (const float*)d_in[3];
    const float* pb    = (const float*)d_in[4];
    const float* ln1g  = (const float*)d_in[5];
    const float* ln1b  = (const float*)d_in[6];
    const float* qkvw  = (const float*)d_in[7];
    const float* outw  = (const float*)d_in[8];
    const float* outb  = (const float*)d_in[9];
    const float* ln2g  = (const float*)d_in[10];
    const float* ln2b  = (const float*)d_in[11];
    const float* ff1w  = (const float*)d_in[12];
    const float* ff1b  = (const float*)d_in[13];
    const float* ff2w  = (const float*)d_in[14];
    const float* ff2b  = (const float*)d_in[15];
    float* out = (float*)d_out;

    float *pX, *pY, *pQKV, *pS, *pO, *pH, *pP;
    cudaGetSymbolAddress((void**)&pX,   g_X);
    cudaGetSymbolAddress((void**)&pY,   g_Y);
    cudaGetSymbolAddress((void**)&pQKV, g_QKV);
    cudaGetSymbolAddress((void**)&pS,   g_S);
    cudaGetSymbolAddress((void**)&pO,   g_O);
    cudaGetSymbolAddress((void**)&pH,   g_H);
    cudaGetSymbolAddress((void**)&pP,   g_P);

    const int Mfull = BATCH * SEQ;      // 4616
    const int Mpat  = BATCH * NPATCH;   // 4608

    // 1) patchify + patch embed + assemble
    patchify_kernel<<<(BATCH * NPATCH * PDIM + 255) / 256, 256>>>(img);
    gemm_kernel<<<gemm_grid(Mpat, DIM, 1), 256>>>(
        pP, PDIM, 0, 0,  pw, DIM, 0, 0, 0,  pb,
        pY, DIM, 0, 0,  Mpat, DIM, PDIM, 0);
    assemble_kernel<<<(BATCH * SEQ * DIM + 255) / 256, 256>>>(pY, cls, pos);

    // 2) transformer layers
    for (int l = 0; l < DEPTH; l++) {
        const float* wqkv = qkvw + (long long)l * DIM * 3 * DIM;
        const float* wo   = outw + (long long)l * DIM * DIM;
        const float* bo   = outb + (long long)l * DIM;
        const float* w1   = ff1w + (long long)l * DIM * MLPD;
        const float* b1   = ff1b + (long long)l * MLPD;
        const float* w2   = ff2w + (long long)l * MLPD * DIM;
        const float* b2   = ff2b + (long long)l * DIM;

        // LN1
        layernorm_kernel<<<Mfull, 256>>>(pX, ln1g + (long long)l * DIM,
                                         ln1b + (long long)l * DIM, pY);
        // QKV = Y @ Wqkv
        gemm_kernel<<<gemm_grid(Mfull, 3 * DIM, 1), 256>>>(
            pY, DIM, 0, 0,  wqkv, 3 * DIM, 0, 0, 0,  nullptr,
            pQKV, 3 * DIM, 0, 0,  Mfull, 3 * DIM, DIM, 0);
        // S = Q @ K^T per (b,h)
        gemm_kernel<<<gemm_grid(SEQ, SEQ, BATCH * HEADS), 256>>>(
            pQKV,              3 * DIM, (long long)SEQ * 3 * DIM, HDIM,
            pQKV + DIM,        3 * DIM, (long long)SEQ * 3 * DIM, HDIM, 1,
            nullptr,
            pS, SEQ, (long long)HEADS * SEQ * SEQ, (long long)SEQ * SEQ,
            SEQ, SEQ, HDIM, 0);
        // softmax rows
        softmax_kernel<<<BATCH * HEADS * SEQ, 256>>>(pS);
        // O = P @ V per (b,h)
        gemm_kernel<<<gemm_grid(SEQ, HDIM, BATCH * HEADS), 256>>>(
            pS, SEQ, (long long)HEADS * SEQ * SEQ, (long long)SEQ * SEQ,
            pQKV + 2 * DIM,    3 * DIM, (long long)SEQ * 3 * DIM, HDIM, 0,
            nullptr,
            pO, DIM, (long long)SEQ * DIM, HDIM,
            SEQ, HDIM, SEQ, 0);
        // X += O @ Wo + bo
        gemm_kernel<<<gemm_grid(Mfull, DIM, 1), 256>>>(
            pO, DIM, 0, 0,  wo, DIM, 0, 0, 0,  bo,
            pX, DIM, 0, 0,  Mfull, DIM, DIM, 2);
        // LN2
        layernorm_kernel<<<Mfull, 256>>>(pX, ln2g + (long long)l * DIM,
                                         ln2b + (long long)l * DIM, pY);
        // H = gelu(Y @ W1 + b1)
        gemm_kernel<<<gemm_grid(Mfull, MLPD, 1), 256>>>(
            pY, DIM, 0, 0,  w1, MLPD, 0, 0, 0,  b1,
            pH, MLPD, 0, 0,  Mfull, MLPD, DIM, 1);
        // X += H @ W2 + b2
        gemm_kernel<<<gemm_grid(Mfull, DIM, 1), 256>>>(
            pH, MLPD, 0, 0,  w2, DIM, 0, 0, 0,  b2,
            pX, DIM, 0, 0,  Mfull, DIM, MLPD, 2);
    }

    // 3) drop cls token -> output
    output_kernel<<<(BATCH * NPATCH * DIM + 255) / 256, 256>>>(out);
}

// round 2
// speedup vs baseline: 3.0469x; 3.0469x over previous
#include <cuda_runtime.h>
#include <math.h>

#define BATCH  8
#define SEQ    577
#define DIM    768
#define HEADS  12
#define HDIM   64
#define MLPD   3072
#define DEPTH  8
#define NPATCH 576
#define PDIM   768
#define IMGH   384
#define PSZ    16
#define HP     24

// ---------------- scratch (device globals; allocation is banned) ------------
__device__ float g_X  [BATCH * SEQ * DIM];        // residual stream
__device__ float g_Y  [BATCH * SEQ * DIM];        // LN output / patch-embed tmp
__device__ float g_QKV[BATCH * SEQ * 3 * DIM];    // fused qkv
__device__ float g_S  [BATCH * HEADS * SEQ * SEQ];// attention scores
__device__ float g_O  [BATCH * SEQ * DIM];        // attn output (pre-proj)
__device__ float g_H  [BATCH * SEQ * MLPD];       // mlp hidden
__device__ float g_P  [BATCH * NPATCH * PDIM];    // patchified image

// ---------------- tf32 helpers ----------------------------------------------
__device__ __forceinline__ unsigned f2tf(float f) {
    unsigned u;
    asm("cvt.rna.tf32.f32 %0, %1;" : "=r"(u) : "f"(f));
    return u;
}

#define MMA_TF32(d, a, b)                                                     \
    asm volatile("mma.sync.aligned.m16n8k8.row.col.f32.tf32.tf32.f32 "        \
                 "{%0,%1,%2,%3}, {%4,%5,%6,%7}, {%8,%9}, {%0,%1,%2,%3};\n"    \
                 : "+f"(d[0]), "+f"(d[1]), "+f"(d[2]), "+f"(d[3])             \
                 : "r"(a[0]), "r"(a[1]), "r"(a[2]), "r"(a[3]),                \
                   "r"(b[0]), "r"(b[1]))

// ---------------- generic batched tf32 tensor-core GEMM ----------------------
// C[z] = op( A[z] @ B[z] (+ bias) ), fuse: 0=none, 1=gelu(exact), 2=residual
// A row-major [M,K] (lda), B row-major [K,N] (ldb) or transB: [N,K] (ldb)
template<int BM, int BN, int BK, int WM, int WN>
__global__ void __launch_bounds__(WM * WN * 32)
gemm_tc(const float* __restrict__ A, int lda, long long sAb, long long sAh, int vecA,
        const float* __restrict__ Bm, int ldb, long long sBb, long long sBh, int transB,
        const float* __restrict__ bias,
        float* __restrict__ C, int ldc, long long sCb, long long sCh,
        int M, int N, int K, int fuse)
{
    constexpr int NTHREADS = WM * WN * 32;
    constexpr int MT = (BM / WM) / 16;   // m16 tiles per warp
    constexpr int NT = (BN / WN) / 8;    // n8  tiles per warp

    __shared__ unsigned As[BM][BK + 8];  // [m][k]
    __shared__ unsigned Bs[BK][BN + 8];  // [k][n]

    int z  = blockIdx.z;
    int zb = z / HEADS, zh = z % HEADS;
    A  += zb * sAb + zh * sAh;
    Bm += zb * sBb + zh * sBh;
    C  += zb * sCb + zh * sCh;

    int r0 = blockIdx.y * BM;
    int c0 = blockIdx.x * BN;
    int tid  = threadIdx.x;
    int wid  = tid >> 5, lane = tid & 31;
    int wm   = wid / WN, wn = wid % WN;
    int q    = lane >> 2, r = lane & 3;

    float acc[MT][NT][4];
    #pragma unroll
    for (int i = 0; i < MT; i++)
        #pragma unroll
        for (int j = 0; j < NT; j++)
            #pragma unroll
            for (int t = 0; t < 4; t++) acc[i][j][t] = 0.f;

    for (int k0 = 0; k0 < K; k0 += BK) {
        // ---- load A tile (BM x BK) into As[m][k] ----
        constexpr int A_IT = BM * BK / (NTHREADS * 4);
        if (vecA) {
            #pragma unroll
            for (int it = 0; it < A_IT; it++) {
                int idx = (tid + it * NTHREADS) * 4;
                int m = idx / BK, kk = idx % BK;
                float4 v = make_float4(0.f, 0.f, 0.f, 0.f);
                if (r0 + m < M) {
                    const float* p = A + (long long)(r0 + m) * lda + k0 + kk;
                    if (k0 + kk + 3 < K) {
                        v = *(const float4*)p;
                    } else {
                        if (k0 + kk     < K) v.x = p[0];
                        if (k0 + kk + 1 < K) v.y = p[1];
                        if (k0 + kk + 2 < K) v.z = p[2];
                        if (k0 + kk + 3 < K) v.w = p[3];
                    }
                }
                As[m][kk + 0] = f2tf(v.x);
                As[m][kk + 1] = f2tf(v.y);
                As[m][kk + 2] = f2tf(v.z);
                As[m][kk + 3] = f2tf(v.w);
            }
        } else {
            #pragma unroll
            for (int it = 0; it < A_IT; it++) {
                int idx = (tid + it * NTHREADS) * 4;
                int m = idx / BK, kk = idx % BK;
                const float* p = A + (long long)(r0 + m) * lda + k0 + kk;
                bool rok = (r0 + m < M);
                #pragma unroll
                for (int e = 0; e < 4; e++) {
                    float v = (rok && k0 + kk + e < K) ? p[e] : 0.f;
                    As[m][kk + e] = f2tf(v);
                }
            }
        }
        // ---- load B tile (BK x BN) into Bs[k][n] ----
        constexpr int B_IT = BK * BN / (NTHREADS * 4);
        if (!transB) {
            #pragma unroll
            for (int it = 0; it < B_IT; it++) {
                int idx = (tid + it * NTHREADS) * 4;
                int kk = idx / BN, n = idx % BN;
                float4 v = make_float4(0.f, 0.f, 0.f, 0.f);
                if (k0 + kk < K) {
                    const float* p = Bm + (long long)(k0 + kk) * ldb + c0 + n;
                    if (c0 + n + 3 < N) {
                        v = *(const float4*)p;
                    } else {
                        if (c0 + n     < N) v.x = p[0];
                        if (c0 + n + 1 < N) v.y = p[1];
                        if (c0 + n + 2 < N) v.z = p[2];
                        if (c0 + n + 3 < N) v.w = p[3];
                    }
                }
                Bs[kk][n + 0] = f2tf(v.x);
                Bs[kk][n + 1] = f2tf(v.y);
                Bs[kk][n + 2] = f2tf(v.z);
                Bs[kk][n + 3] = f2tf(v.w);
            }
        } else {
            // B global is [N,K]; read along k, scatter to Bs[k][n]
            #pragma unroll
            for (int it = 0; it < B_IT; it++) {
                int idx = (tid + it * NTHREADS) * 4;
                int n = idx / BK, kk = idx % BK;
                float4 v = make_float4(0.f, 0.f, 0.f, 0.f);
                if (c0 + n < N) {
                    const float* p = Bm + (long long)(c0 + n) * ldb + k0 + kk;
                    if (k0 + kk + 3 < K) {
                        v = *(const float4*)p;
                    } else {
                        if (k0 + kk     < K) v.x = p[0];
                        if (k0 + kk + 1 < K) v.y = p[1];
                        if (k0 + kk + 2 < K) v.z = p[2];
                        if (k0 + kk + 3 < K) v.w = p[3];
                    }
                }
                Bs[kk + 0][n] = f2tf(v.x);
                Bs[kk + 1][n] = f2tf(v.y);
                Bs[kk + 2][n] = f2tf(v.z);
                Bs[kk + 3][n] = f2tf(v.w);
            }
        }
        __syncthreads();

        // ---- compute ----
        #pragma unroll
        for (int kk = 0; kk < BK; kk += 8) {
            unsigned af[MT][4];
            unsigned bf[NT][2];
            #pragma unroll
            for (int i = 0; i < MT; i++) {
                int m = wm * (BM / WM) + i * 16;
                af[i][0] = As[m + q    ][kk + r    ];
                af[i][1] = As[m + q + 8][kk + r    ];
                af[i][2] = As[m + q    ][kk + r + 4];
                af[i][3] = As[m + q + 8][kk + r + 4];
            }
            #pragma unroll
            for (int j = 0; j < NT; j++) {
                int n = wn * (BN / WN) + j * 8;
                bf[j][0] = Bs[kk + r    ][n + q];
                bf[j][1] = Bs[kk + r + 4][n + q];
            }
            #pragma unroll
            for (int i = 0; i < MT; i++)
                #pragma unroll
                for (int j = 0; j < NT; j++)
                    MMA_TF32(acc[i][j], af[i], bf[j]);
        }
        __syncthreads();
    }

    // ---- epilogue ----
    #pragma unroll
    for (int i = 0; i < MT; i++) {
        #pragma unroll
        for (int j = 0; j < NT; j++) {
            #pragma unroll
            for (int t = 0; t < 4; t++) {
                int row = r0 + wm * (BM / WM) + i * 16 + q + ((t >= 2) ? 8 : 0);
                int col = c0 + wn * (BN / WN) + j * 8 + r * 2 + (t & 1);
                if (row >= M || col >= N) continue;
                float v = acc[i][j][t];
                if (bias) v += bias[col];
                if (fuse == 1) v = 0.5f * v * (1.f + erff(v * 0.70710678118654752f));
                long long off = (long long)row * ldc + col;
                if (fuse == 2) v += C[off];
                C[off] = v;
            }
        }
    }
}

// ---------------- reductions -------------------------------------------------
__device__ __forceinline__ float blockReduceSum(float v, volatile float* sh) {
    int lane = threadIdx.x & 31, w = threadIdx.x >> 5;
    #pragma unroll
    for (int o = 16; o; o >>= 1) v += __shfl_down_sync(0xffffffffu, v, o);
    if (lane == 0) sh[w] = v;
    __syncthreads();
    if (threadIdx.x < 32) {
        v = (threadIdx.x < 8) ? sh[threadIdx.x] : 0.f;
        #pragma unroll
        for (int o = 4; o; o >>= 1) v += __shfl_down_sync(0xffffffffu, v, o);
        if (lane == 0) sh[0] = v;
    }
    __syncthreads();
    return sh[0];
}

__device__ __forceinline__ float blockReduceMax(float v, volatile float* sh) {
    int lane = threadIdx.x & 31, w = threadIdx.x >> 5;
    #pragma unroll
    for (int o = 16; o; o >>= 1) v = fmaxf(v, __shfl_down_sync(0xffffffffu, v, o));
    if (lane == 0) sh[w] = v;
    __syncthreads();
    if (threadIdx.x < 32) {
        v = (threadIdx.x < 8) ? sh[threadIdx.x] : -3.0e38f;
        #pragma unroll
        for (int o = 4; o; o >>= 1) v = fmaxf(v, __shfl_down_sync(0xffffffffu, v, o));
        if (lane == 0) sh[0] = v;
    }
    __syncthreads();
    return sh[0];
}

// ---------------- layernorm --------------------------------------------------
__global__ void __launch_bounds__(256)
layernorm_kernel(const float* __restrict__ X, const float* __restrict__ g,
                 const float* __restrict__ b, float* __restrict__ Y)
{
    long long row = blockIdx.x;
    const float* x = X + row * DIM;
    __shared__ float sh0[8], sh1[8];
    float v0 = x[threadIdx.x], v1 = x[threadIdx.x + 256], v2 = x[threadIdx.x + 512];
    float sum  = blockReduceSum(v0 + v1 + v2, sh0);
    float sum2 = blockReduceSum(v0 * v0 + v1 * v1 + v2 * v2, sh1);
    float m   = sum * (1.f / DIM);
    float var = sum2 * (1.f / DIM) - m * m;
    float inv = rsqrtf(var + 1e-5f);
    float* y = Y + row * DIM;
    #pragma unroll
    for (int i = 0; i < 3; i++) {
        int c = threadIdx.x + i * 256;
        float xv = (i == 0) ? v0 : (i == 1) ? v1 : v2;
        y[c] = (xv - m) * inv * g[c] + b[c];
    }
}

// ---------------- softmax (in place over last dim SEQ) -----------------------
__global__ void __launch_bounds__(256)
softmax_kernel(float* __restrict__ S)
{
    long long row = blockIdx.x;
    float* p = S + row * SEQ;
    __shared__ float sh[8];
    float mx = -3.0e38f;
    for (int c = threadIdx.x; c < SEQ; c += 256) mx = fmaxf(mx, p[c]);
    mx = blockReduceMax(mx, sh);
    __syncthreads();
    float s = 0.f;
    for (int c = threadIdx.x; c < SEQ; c += 256) {
        float e = __expf(p[c] - mx);
        p[c] = e;
        s += e;
    }
    s = blockReduceSum(s, sh);
    float inv = 1.f / s;
    for (int c = threadIdx.x; c < SEQ; c += 256) p[c] *= inv;
}

// ---------------- patchify ----------------------------------------------------
__global__ void __launch_bounds__(256)
patchify_kernel(const float* __restrict__ img)
{
    int idx = blockIdx.x * 256 + threadIdx.x;
    if (idx >= BATCH * NPATCH * PDIM) return;
    int pd = idx % PDIM;
    int t  = idx / PDIM;
    int patch = t % NPATCH;
    int b     = t / NPATCH;
    int c  = pd % 3;
    int pp = pd / 3;
    int p2 = pp % PSZ, p1 = pp / PSZ;
    int wx = patch % HP, hy = patch / HP;
    g_P[idx] = img[(((long long)b * 3 + c) * IMGH + hy * PSZ + p1) * IMGH + wx * PSZ + p2];
}

// ---------------- assemble: cls + pos add ------------------------------------
__global__ void __launch_bounds__(256)
assemble_kernel(const float* __restrict__ emb, const float* __restrict__ cls,
                const float* __restrict__ pos)
{
    int idx = blockIdx.x * 256 + threadIdx.x;
    if (idx >= BATCH * SEQ * DIM) return;
    int d = idx % DIM;
    int t = idx / DIM;
    int s = t % SEQ;
    int b = t / SEQ;
    float v;
    if (s == 0) v = cls[d] + pos[d];
    else        v = emb[((long long)b * NPATCH + (s - 1)) * DIM + d] + pos[(long long)s * DIM + d];
    g_X[idx] = v;
}

// ---------------- output: drop cls token -------------------------------------
__global__ void __launch_bounds__(256)
output_kernel(float* __restrict__ out)
{
    int idx = blockIdx.x * 256 + threadIdx.x;
    if (idx >= BATCH * NPATCH * DIM) return;
    int d = idx % DIM;
    int t = idx / DIM;
    int s = t % NPATCH;
    int b = t / NPATCH;
    out[idx] = g_X[((long long)b * SEQ + (s + 1)) * DIM + d];
}

// ---------------- host driver ------------------------------------------------
extern "C" void kernel_launch(void* const* d_in, const int* in_sizes, int n_in,
                              void* d_out, int out_size)
{
    const float* img   = (const float*)d_in[0];
    const float* pos   = (const float*)d_in[1];
    const float* cls   = (const float*)d_in[2];
    const float* pw    = (const float*)d_in[3];
    const float* pb    = (const float*)d_in[4];
    const float* ln1g  = (const float*)d_in[5];
    const float* ln1b  = (const float*)d_in[6];
    const float* qkvw  = (const float*)d_in[7];
    const float* outw  = (const float*)d_in[8];
    const float* outb  = (const float*)d_in[9];
    const float* ln2g  = (const float*)d_in[10];
    const float* ln2b  = (const float*)d_in[11];
    const float* ff1w  = (const float*)d_in[12];
    const float* ff1b  = (const float*)d_in[13];
    const float* ff2w  = (const float*)d_in[14];
    const float* ff2b  = (const float*)d_in[15];
    float* out = (float*)d_out;

    float *pX, *pY, *pQKV, *pS, *pO, *pH, *pP;
    cudaGetSymbolAddress((void**)&pX,   g_X);
    cudaGetSymbolAddress((void**)&pY,   g_Y);
    cudaGetSymbolAddress((void**)&pQKV, g_QKV);
    cudaGetSymbolAddress((void**)&pS,   g_S);
    cudaGetSymbolAddress((void**)&pO,   g_O);
    cudaGetSymbolAddress((void**)&pH,   g_H);
    cudaGetSymbolAddress((void**)&pP,   g_P);

    const int Mfull = BATCH * SEQ;      // 4616
    const int Mpat  = BATCH * NPATCH;   // 4608

    auto grid = [](int M, int N, int BMv, int BNv, int Z) {
        return dim3((N + BNv - 1) / BNv, (M + BMv - 1) / BMv, Z);
    };

    // 1) patchify + patch embed + assemble
    patchify_kernel<<<(BATCH * NPATCH * PDIM + 255) / 256, 256>>>(img);
    gemm_tc<128,128,32,2,4><<<grid(Mpat, DIM, 128, 128, 1), 256>>>(
        pP, PDIM, 0, 0, 1,  pw, DIM, 0, 0, 0,  pb,
        pY, DIM, 0, 0,  Mpat, DIM, PDIM, 0);
    assemble_kernel<<<(BATCH * SEQ * DIM + 255) / 256, 256>>>(pY, cls, pos);

    // 2) transformer layers
    for (int l = 0; l < DEPTH; l++) {
        const float* wqkv = qkvw + (long long)l * DIM * 3 * DIM;
        const float* wo   = outw + (long long)l * DIM * DIM;
        const float* bo   = outb + (long long)l * DIM;
        const float* w1   = ff1w + (long long)l * DIM * MLPD;
        const float* b1   = ff1b + (long long)l * MLPD;
        const float* w2   = ff2w + (long long)l * MLPD * DIM;
        const float* b2   = ff2b + (long long)l * DIM;

        // LN1
        layernorm_kernel<<<Mfull, 256>>>(pX, ln1g + (long long)l * DIM,
                                         ln1b + (long long)l * DIM, pY);
        // QKV = Y @ Wqkv
        gemm_tc<128,128,32,2,4><<<grid(Mfull, 3 * DIM, 128, 128, 1), 256>>>(
            pY, DIM, 0, 0, 1,  wqkv, 3 * DIM, 0, 0, 0,  nullptr,
            pQKV, 3 * DIM, 0, 0,  Mfull, 3 * DIM, DIM, 0);
        // S = Q @ K^T per (b,h)
        gemm_tc<128,128,32,2,4><<<grid(SEQ, SEQ, 128, 128, BATCH * HEADS), 256>>>(
            pQKV,       3 * DIM, (long long)SEQ * 3 * DIM, HDIM, 1,
            pQKV + DIM, 3 * DIM, (long long)SEQ * 3 * DIM, HDIM, 1,
            nullptr,
            pS, SEQ, (long long)HEADS * SEQ * SEQ, (long long)SEQ * SEQ,
            SEQ, SEQ, HDIM, 0);
        // softmax rows
        softmax_kernel<<<BATCH * HEADS * SEQ, 256>>>(pS);
        // O = P @ V per (b,h)  (A = scores, lda=577 unaligned -> vecA=0)
        gemm_tc<128,64,32,4,2><<<grid(SEQ, HDIM, 128, 64, BATCH * HEADS), 256>>>(
            pS, SEQ, (long long)HEADS * SEQ * SEQ, (long long)SEQ * SEQ, 0,
            pQKV + 2 * DIM, 3 * DIM, (long long)SEQ * 3 * DIM, HDIM, 0,
            nullptr,
            pO, DIM, (long long)SEQ * DIM, HDIM,
            SEQ, HDIM, SEQ, 0);
        // X += O @ Wo + bo
        gemm_tc<128,128,32,2,4><<<grid(Mfull, DIM, 128, 128, 1), 256>>>(
            pO, DIM, 0, 0, 1,  wo, DIM, 0, 0, 0,  bo,
            pX, DIM, 0, 0,  Mfull, DIM, DIM, 2);
        // LN2
        layernorm_kernel<<<Mfull, 256>>>(pX, ln2g + (long long)l * DIM,
                                         ln2b + (long long)l * DIM, pY);
        // H = gelu(Y @ W1 + b1)
        gemm_tc<128,128,32,2,4><<<grid(Mfull, MLPD, 128, 128, 1), 256>>>(
            pY, DIM, 0, 0, 1,  w1, MLPD, 0, 0, 0,  b1,
            pH, MLPD, 0, 0,  Mfull, MLPD, DIM, 1);
        // X += H @ W2 + b2
        gemm_tc<128,128,32,2,4><<<grid(Mfull, DIM, 128, 128, 1), 256>>>(
            pH, MLPD, 0, 0, 1,  w2, DIM, 0, 0, 0,  b2,
            pX, DIM, 0, 0,  Mfull, DIM, MLPD, 2);
    }

    // 3) drop cls token -> output
    output_kernel<<<(BATCH * NPATCH * DIM + 255) / 256, 256>>>(out);
}

// round 3
// speedup vs baseline: 4.5789x; 1.5028x over previous
#include <cuda_runtime.h>
#include <math.h>

#define BATCH  8
#define SEQ    577
#define DIM    768
#define HEADS  12
#define HDIM   64
#define MLPD   3072
#define DEPTH  8
#define NPATCH 576
#define PDIM   768
#define IMGH   384
#define PSZ    16
#define HP     24

// ---------------- scratch (device globals; allocation is banned) ------------
__device__ float g_X  [BATCH * SEQ * DIM];
__device__ float g_Y  [BATCH * SEQ * DIM];
__device__ float g_QKV[BATCH * SEQ * 3 * DIM];
__device__ float g_S  [BATCH * HEADS * SEQ * SEQ];
__device__ float g_O  [BATCH * SEQ * DIM];
__device__ float g_H  [BATCH * SEQ * MLPD];
__device__ float g_P  [BATCH * NPATCH * PDIM];

// ---------------- tf32 helpers ----------------------------------------------
__device__ __forceinline__ unsigned f2tf(float f) {
    unsigned u;
    asm("cvt.rna.tf32.f32 %0, %1;" : "=r"(u) : "f"(f));
    return u;
}

#define MMA_TF32(d, a, b)                                                     \
    asm volatile("mma.sync.aligned.m16n8k8.row.col.f32.tf32.tf32.f32 "        \
                 "{%0,%1,%2,%3}, {%4,%5,%6,%7}, {%8,%9}, {%0,%1,%2,%3};\n"    \
                 : "+f"(d[0]), "+f"(d[1]), "+f"(d[2]), "+f"(d[3])             \
                 : "r"(a[0]), "r"(a[1]), "r"(a[2]), "r"(a[3]),                \
                   "r"(b[0]), "r"(b[1]))

// ---------------- generic batched tf32 tensor-core GEMM ----------------------
// C[z] = op( A[z] @ B[z] (+ bias) ), fuse: 0=none, 1=gelu(exact), 2=residual
// Software-pipelined: global loads for tile t+1 staged in registers while
// computing tile t. Smem pads chosen for conflict-free fragment loads.
template<int BM, int BN, int BK, int WM, int WN>
__global__ void __launch_bounds__(WM * WN * 32)
gemm_tc(const float* __restrict__ A, int lda, long long sAb, long long sAh, int vecA,
        const float* __restrict__ Bm, int ldb, long long sBb, long long sBh, int transB,
        const float* __restrict__ bias,
        float* __restrict__ C, int ldc, long long sCb, long long sCh,
        int M, int N, int K, int fuse)
{
    constexpr int NTHREADS = WM * WN * 32;
    constexpr int MT = (BM / WM) / 16;
    constexpr int NT = (BN / WN) / 8;
    constexpr int A_IT = BM * BK / (NTHREADS * 4);
    constexpr int B_IT = BK * BN / (NTHREADS * 4);
    constexpr int APAD = 4;               // row stride 36 -> banks 4q+r (conflict-free)
    constexpr int BPAD = 4;               // row stride BN+4 -> banks 4r+q (conflict-free)

    __shared__ unsigned As[BM][BK + APAD];   // [m][k]
    __shared__ unsigned Bs[BK][BN + BPAD];   // [k][n]

    int z  = blockIdx.z;
    int zb = z / HEADS, zh = z % HEADS;
    A  += zb * sAb + zh * sAh;
    Bm += zb * sBb + zh * sBh;
    C  += zb * sCb + zh * sCh;

    int r0 = blockIdx.y * BM;
    int c0 = blockIdx.x * BN;
    int tid  = threadIdx.x;
    int wid  = tid >> 5, lane = tid & 31;
    int wm   = wid / WN, wn = wid % WN;
    int q    = lane >> 2, r = lane & 3;

    float acc[MT][NT][4];
    #pragma unroll
    for (int i = 0; i < MT; i++)
        #pragma unroll
        for (int j = 0; j < NT; j++)
            #pragma unroll
            for (int t = 0; t < 4; t++) acc[i][j][t] = 0.f;

    float4 rA[A_IT], rB[B_IT];

    // ---- global load of one k-tile into registers ----
    auto gloadA = [&](int k0) {
        #pragma unroll
        for (int it = 0; it < A_IT; it++) {
            int idx = (tid + it * NTHREADS) * 4;
            int m = idx / BK, kk = idx % BK;
            float4 v = make_float4(0.f, 0.f, 0.f, 0.f);
            if (r0 + m < M) {
                const float* p = A + (long long)(r0 + m) * lda + k0 + kk;
                if (vecA && k0 + kk + 3 < K) {
                    v = *(const float4*)p;
                } else {
                    if (k0 + kk     < K) v.x = p[0];
                    if (k0 + kk + 1 < K) v.y = p[1];
                    if (k0 + kk + 2 < K) v.z = p[2];
                    if (k0 + kk + 3 < K) v.w = p[3];
                }
            }
            rA[it] = v;
        }
    };
    auto gloadB = [&](int k0) {
        if (!transB) {
            #pragma unroll
            for (int it = 0; it < B_IT; it++) {
                int idx = (tid + it * NTHREADS) * 4;
                int kk = idx / BN, n = idx % BN;
                float4 v = make_float4(0.f, 0.f, 0.f, 0.f);
                if (k0 + kk < K) {
                    const float* p = Bm + (long long)(k0 + kk) * ldb + c0 + n;
                    if (c0 + n + 3 < N) {
                        v = *(const float4*)p;
                    } else {
                        if (c0 + n     < N) v.x = p[0];
                        if (c0 + n + 1 < N) v.y = p[1];
                        if (c0 + n + 2 < N) v.z = p[2];
                        if (c0 + n + 3 < N) v.w = p[3];
                    }
                }
                rB[it] = v;
            }
        } else {
            #pragma unroll
            for (int it = 0; it < B_IT; it++) {
                int idx = (tid + it * NTHREADS) * 4;
                int n = idx / BK, kk = idx % BK;
                float4 v = make_float4(0.f, 0.f, 0.f, 0.f);
                if (c0 + n < N) {
                    const float* p = Bm + (long long)(c0 + n) * ldb + k0 + kk;
                    if (k0 + kk + 3 < K) {
                        v = *(const float4*)p;
                    } else {
                        if (k0 + kk     < K) v.x = p[0];
                        if (k0 + kk + 1 < K) v.y = p[1];
                        if (k0 + kk + 2 < K) v.z = p[2];
                        if (k0 + kk + 3 < K) v.w = p[3];
                    }
                }
                rB[it] = v;
            }
        }
    };
    // ---- stage registers -> smem (with rna tf32 conversion) ----
    auto sstore = [&]() {
        #pragma unroll
        for (int it = 0; it < A_IT; it++) {
            int idx = (tid + it * NTHREADS) * 4;
            int m = idx / BK, kk = idx % BK;
            As[m][kk + 0] = f2tf(rA[it].x);
            As[m][kk + 1] = f2tf(rA[it].y);
            As[m][kk + 2] = f2tf(rA[it].z);
            As[m][kk + 3] = f2tf(rA[it].w);
        }
        if (!transB) {
            #pragma unroll
            for (int it = 0; it < B_IT; it++) {
                int idx = (tid + it * NTHREADS) * 4;
                int kk = idx / BN, n = idx % BN;
                Bs[kk][n + 0] = f2tf(rB[it].x);
                Bs[kk][n + 1] = f2tf(rB[it].y);
                Bs[kk][n + 2] = f2tf(rB[it].z);
                Bs[kk][n + 3] = f2tf(rB[it].w);
            }
        } else {
            #pragma unroll
            for (int it = 0; it < B_IT; it++) {
                int idx = (tid + it * NTHREADS) * 4;
                int n = idx / BK, kk = idx % BK;
                Bs[kk + 0][n] = f2tf(rB[it].x);
                Bs[kk + 1][n] = f2tf(rB[it].y);
                Bs[kk + 2][n] = f2tf(rB[it].z);
                Bs[kk + 3][n] = f2tf(rB[it].w);
            }
        }
    };

    int T = (K + BK - 1) / BK;
    gloadA(0); gloadB(0);

    for (int t = 0; t < T; t++) {
        sstore();
        __syncthreads();
        if (t + 1 < T) {                 // prefetch next tile; LDG latency
            gloadA((t + 1) * BK);        // overlaps the MMA loop below
            gloadB((t + 1) * BK);
        }
        #pragma unroll
        for (int kk = 0; kk < BK; kk += 8) {
            unsigned af[MT][4];
            unsigned bf[NT][2];
            #pragma unroll
            for (int i = 0; i < MT; i++) {
                int m = wm * (BM / WM) + i * 16;
                af[i][0] = As[m + q    ][kk + r    ];
                af[i][1] = As[m + q + 8][kk + r    ];
                af[i][2] = As[m + q    ][kk + r + 4];
                af[i][3] = As[m + q + 8][kk + r + 4];
            }
            #pragma unroll
            for (int j = 0; j < NT; j++) {
                int n = wn * (BN / WN) + j * 8;
                bf[j][0] = Bs[kk + r    ][n + q];
                bf[j][1] = Bs[kk + r + 4][n + q];
            }
            #pragma unroll
            for (int i = 0; i < MT; i++)
                #pragma unroll
                for (int j = 0; j < NT; j++)
                    MMA_TF32(acc[i][j], af[i], bf[j]);
        }
        __syncthreads();
    }

    // ---- epilogue ----
    #pragma unroll
    for (int i = 0; i < MT; i++) {
        #pragma unroll
        for (int j = 0; j < NT; j++) {
            #pragma unroll
            for (int t = 0; t < 4; t++) {
                int row = r0 + wm * (BM / WM) + i * 16 + q + ((t >= 2) ? 8 : 0);
                int col = c0 + wn * (BN / WN) + j * 8 + r * 2 + (t & 1);
                if (row >= M || col >= N) continue;
                float v = acc[i][j][t];
                if (bias) v += bias[col];
                if (fuse == 1) v = 0.5f * v * (1.f + erff(v * 0.70710678118654752f));
                long long off = (long long)row * ldc + col;
                if (fuse == 2) v += C[off];
                C[off] = v;
            }
        }
    }
}

// ---------------- reductions -------------------------------------------------
__device__ __forceinline__ float blockReduceSum(float v, volatile float* sh) {
    int lane = threadIdx.x & 31, w = threadIdx.x >> 5;
    #pragma unroll
    for (int o = 16; o; o >>= 1) v += __shfl_down_sync(0xffffffffu, v, o);
    if (lane == 0) sh[w] = v;
    __syncthreads();
    if (threadIdx.x < 32) {
        v = (threadIdx.x < 8) ? sh[threadIdx.x] : 0.f;
        #pragma unroll
        for (int o = 4; o; o >>= 1) v += __shfl_down_sync(0xffffffffu, v, o);
        if (lane == 0) sh[0] = v;
    }
    __syncthreads();
    return sh[0];
}

__device__ __forceinline__ float blockReduceMax(float v, volatile float* sh) {
    int lane = threadIdx.x & 31, w = threadIdx.x >> 5;
    #pragma unroll
    for (int o = 16; o; o >>= 1) v = fmaxf(v, __shfl_down_sync(0xffffffffu, v, o));
    if (lane == 0) sh[w] = v;
    __syncthreads();
    if (threadIdx.x < 32) {
        v = (threadIdx.x < 8) ? sh[threadIdx.x] : -3.0e38f;
        #pragma unroll
        for (int o = 4; o; o >>= 1) v = fmaxf(v, __shfl_down_sync(0xffffffffu, v, o));
        if (lane == 0) sh[0] = v;
    }
    __syncthreads();
    return sh[0];
}

// ---------------- layernorm --------------------------------------------------
__global__ void __launch_bounds__(256)
layernorm_kernel(const float* __restrict__ X, const float* __restrict__ g,
                 const float* __restrict__ b, float* __restrict__ Y)
{
    long long row = blockIdx.x;
    const float* x = X + row * DIM;
    __shared__ float sh0[8], sh1[8];
    float v0 = x[threadIdx.x], v1 = x[threadIdx.x + 256], v2 = x[threadIdx.x + 512];
    float sum  = blockReduceSum(v0 + v1 + v2, sh0);
    float sum2 = blockReduceSum(v0 * v0 + v1 * v1 + v2 * v2, sh1);
    float m   = sum * (1.f / DIM);
    float var = sum2 * (1.f / DIM) - m * m;
    float inv = rsqrtf(var + 1e-5f);
    float* y = Y + row * DIM;
    #pragma unroll
    for (int i = 0; i < 3; i++) {
        int c = threadIdx.x + i * 256;
        float xv = (i == 0) ? v0 : (i == 1) ? v1 : v2;
        y[c] = (xv - m) * inv * g[c] + b[c];
    }
}

// ---------------- softmax (in place over last dim SEQ) -----------------------
__global__ void __launch_bounds__(256)
softmax_kernel(float* __restrict__ S)
{
    long long row = blockIdx.x;
    float* p = S + row * SEQ;
    __shared__ float sh[8];
    float mx = -3.0e38f;
    for (int c = threadIdx.x; c < SEQ; c += 256) mx = fmaxf(mx, p[c]);
    mx = blockReduceMax(mx, sh);
    __syncthreads();
    float s = 0.f;
    for (int c = threadIdx.x; c < SEQ; c += 256) {
        float e = __expf(p[c] - mx);
        p[c] = e;
        s += e;
    }
    s = blockReduceSum(s, sh);
    float inv = 1.f / s;
    for (int c = threadIdx.x; c < SEQ; c += 256) p[c] *= inv;
}

// ---------------- patchify ----------------------------------------------------
__global__ void __launch_bounds__(256)
patchify_kernel(const float* __restrict__ img)
{
    int idx = blockIdx.x * 256 + threadIdx.x;
    if (idx >= BATCH * NPATCH * PDIM) return;
    int pd = idx % PDIM;
    int t  = idx / PDIM;
    int patch = t % NPATCH;
    int b     = t / NPATCH;
    int c  = pd % 3;
    int pp = pd / 3;
    int p2 = pp % PSZ, p1 = pp / PSZ;
    int wx = patch % HP, hy = patch / HP;
    g_P[idx] = img[(((long long)b * 3 + c) * IMGH + hy * PSZ + p1) * IMGH + wx * PSZ + p2];
}

// ---------------- assemble: cls + pos add ------------------------------------
__global__ void __launch_bounds__(256)
assemble_kernel(const float* __restrict__ emb, const float* __restrict__ cls,
                const float* __restrict__ pos)
{
    int idx = blockIdx.x * 256 + threadIdx.x;
    if (idx >= BATCH * SEQ * DIM) return;
    int d = idx % DIM;
    int t = idx / DIM;
    int s = t % SEQ;
    int b = t / SEQ;
    float v;
    if (s == 0) v = cls[d] + pos[d];
    else        v = emb[((long long)b * NPATCH + (s - 1)) * DIM + d] + pos[(long long)s * DIM + d];
    g_X[idx] = v;
}

// ---------------- output: drop cls token -------------------------------------
__global__ void __launch_bounds__(256)
output_kernel(float* __restrict__ out)
{
    int idx = blockIdx.x * 256 + threadIdx.x;
    if (idx >= BATCH * NPATCH * DIM) return;
    int d = idx % DIM;
    int t = idx / DIM;
    int s = t % NPATCH;
    int b = t / NPATCH;
    out[idx] = g_X[((long long)b * SEQ + (s + 1)) * DIM + d];
}

// ---------------- host driver ------------------------------------------------
extern "C" void kernel_launch(void* const* d_in, const int* in_sizes, int n_in,
                              void* d_out, int out_size)
{
    const float* img   = (const float*)d_in[0];
    const float* pos   = (const float*)d_in[1];
    const float* cls   = (const float*)d_in[2];
    const float* pw    = (const float*)d_in[3];
    const float* pb    = (const float*)d_in[4];
    const float* ln1g  = (const float*)d_in[5];
    const float* ln1b  = (const float*)d_in[6];
    const float* qkvw  = (const float*)d_in[7];
    const float* outw  = (const float*)d_in[8];
    const float* outb  = (const float*)d_in[9];
    const float* ln2g  = (const float*)d_in[10];
    const float* ln2b  = (const float*)d_in[11];
    const float* ff1w  = (const float*)d_in[12];
    const float* ff1b  = (const float*)d_in[13];
    const float* ff2w  = (const float*)d_in[14];
    const float* ff2b  = (const float*)d_in[15];
    float* out = (float*)d_out;

    float *pX, *pY, *pQKV, *pS, *pO, *pH, *pP;
    cudaGetSymbolAddress((void**)&pX,   g_X);
    cudaGetSymbolAddress((void**)&pY,   g_Y);
    cudaGetSymbolAddress((void**)&pQKV, g_QKV);
    cudaGetSymbolAddress((void**)&pS,   g_S);
    cudaGetSymbolAddress((void**)&pO,   g_O);
    cudaGetSymbolAddress((void**)&pH,   g_H);
    cudaGetSymbolAddress((void**)&pP,   g_P);

    const int Mfull = BATCH * SEQ;
    const int Mpat  = BATCH * NPATCH;

    auto grid = [](int M, int N, int BMv, int BNv, int Z) {
        return dim3((N + BNv - 1) / BNv, (M + BMv - 1) / BMv, Z);
    };

    // 1) patchify + patch embed + assemble
    patchify_kernel<<<(BATCH * NPATCH * PDIM + 255) / 256, 256>>>(img);
    gemm_tc<128,128,32,2,4><<<grid(Mpat, DIM, 128, 128, 1), 256>>>(
        pP, PDIM, 0, 0, 1,  pw, DIM, 0, 0, 0,  pb,
        pY, DIM, 0, 0,  Mpat, DIM, PDIM, 0);
    assemble_kernel<<<(BATCH * SEQ * DIM + 255) / 256, 256>>>(pY, cls, pos);

    // 2) transformer layers
    for (int l = 0; l < DEPTH; l++) {
        const float* wqkv = qkvw + (long long)l * DIM * 3 * DIM;
        const float* wo   = outw + (long long)l * DIM * DIM;
        const float* bo   = outb + (long long)l * DIM;
        const float* w1   = ff1w + (long long)l * DIM * MLPD;
        const float* b1   = ff1b + (long long)l * MLPD;
        const float* w2   = ff2w + (long long)l * MLPD * DIM;
        const float* b2   = ff2b + (long long)l * DIM;

        layernorm_kernel<<<Mfull, 256>>>(pX, ln1g + (long long)l * DIM,
                                         ln1b + (long long)l * DIM, pY);
        gemm_tc<128,128,32,2,4><<<grid(Mfull, 3 * DIM, 128, 128, 1), 256>>>(
            pY, DIM, 0, 0, 1,  wqkv, 3 * DIM, 0, 0, 0,  nullptr,
            pQKV, 3 * DIM, 0, 0,  Mfull, 3 * DIM, DIM, 0);
        gemm_tc<128,128,32,2,4><<<grid(SEQ, SEQ, 128, 128, BATCH * HEADS), 256>>>(
            pQKV,       3 * DIM, (long long)SEQ * 3 * DIM, HDIM, 1,
            pQKV + DIM, 3 * DIM, (long long)SEQ * 3 * DIM, HDIM, 1,
            nullptr,
            pS, SEQ, (long long)HEADS * SEQ * SEQ, (long long)SEQ * SEQ,
            SEQ, SEQ, HDIM, 0);
        softmax_kernel<<<BATCH * HEADS * SEQ, 256>>>(pS);
        gemm_tc<128,64,32,4,2><<<grid(SEQ, HDIM, 128, 64, BATCH * HEADS), 256>>>(
            pS, SEQ, (long long)HEADS * SEQ * SEQ, (long long)SEQ * SEQ, 0,
            pQKV + 2 * DIM, 3 * DIM, (long long)SEQ * 3 * DIM, HDIM, 0,
            nullptr,
            pO, DIM, (long long)SEQ * DIM, HDIM,
            SEQ, HDIM, SEQ, 0);
        gemm_tc<128,128,32,2,4><<<grid(Mfull, DIM, 128, 128, 1), 256>>>(
            pO, DIM, 0, 0, 1,  wo, DIM, 0, 0, 0,  bo,
            pX, DIM, 0, 0,  Mfull, DIM, DIM, 2);
        layernorm_kernel<<<Mfull, 256>>>(pX, ln2g + (long long)l * DIM,
                                         ln2b + (long long)l * DIM, pY);
        gemm_tc<128,128,32,2,4><<<grid(Mfull, MLPD, 128, 128, 1), 256>>>(
            pY, DIM, 0, 0, 1,  w1, MLPD, 0, 0, 0,  b1,
            pH, MLPD, 0, 0,  Mfull, MLPD, DIM, 1);
        gemm_tc<128,128,32,2,4><<<grid(Mfull, DIM, 128, 128, 1), 256>>>(
            pH, MLPD, 0, 0, 1,  w2, DIM, 0, 0, 0,  b2,
            pX, DIM, 0, 0,  Mfull, DIM, MLPD, 2);
    }

    // 3) drop cls token -> output
    output_kernel<<<(BATCH * NPATCH * DIM + 255) / 256, 256>>>(out);
}